// round 5
// baseline (speedup 1.0000x reference)
#include <cuda_runtime.h>
#include <cuda_fp16.h>

#define BATCH  2048
#define LATENT 64
#define NJ     32           // number of j-chunks
#define JC     (BATCH/NJ)   // 64 j per chunk
#define IB     128          // i per CTA
#define NP     (LATENT/2)   // 32 pairs
#define NQ     (LATENT/4)   // 16 quad-records

#define LOG2E_F   1.4426950408889634f
#define LN2_F     0.6931471805599453f
#define LOG2PI_F  1.8378770664093453f

// ---- device scratch (static; no allocation anywhere) ----
__device__ unsigned int d_accP[NJ*NP*BATCH]; // per-(chunk,pair,i) half2 partial sums (8MB)
__device__ float d_m2P[NJ*BATCH];            // per-(chunk,i) running max (log2 domain)
__device__ float d_t2P[NJ*BATCH];            // per-(chunk,i) running scaled sum
__device__ float d_lqp[NP*BATCH];            // per-(pair,i) lg2(s0)+lg2(s1)
__device__ float d_val[BATCH];               // per-i final value
__device__ unsigned int d_ctr;               // last-block counter

// ---- tiny PTX helpers ----
__device__ __forceinline__ float ex2f(float x){ float r; asm("ex2.approx.f32 %0, %1;" : "=f"(r) : "f"(x)); return r; }
__device__ __forceinline__ float lg2f(float x){ float r; asm("lg2.approx.f32 %0, %1;" : "=f"(r) : "f"(x)); return r; }
typedef unsigned long long u64;
__device__ __forceinline__ u64 fma2(u64 a, u64 b, u64 c){ u64 d; asm("fma.rn.f32x2 %0, %1, %2, %3;" : "=l"(d) : "l"(a), "l"(b), "l"(c)); return d; }
__device__ __forceinline__ u64 add2(u64 a, u64 b){ u64 d; asm("add.rn.f32x2 %0, %1, %2;" : "=l"(d) : "l"(a), "l"(b)); return d; }
__device__ __forceinline__ void upk(u64 v, float& lo, float& hi){ asm("mov.b64 {%0, %1}, %2;" : "=f"(lo), "=f"(hi) : "l"(v)); }
__device__ __forceinline__ u64 pkf2(float lo, float hi){ u64 r; asm("mov.b64 %0, {%1, %2};" : "=l"(r) : "f"(lo), "f"(hi)); return r; }
__device__ __forceinline__ unsigned cvt_h2(float a, float b){ unsigned r; asm("cvt.rn.f16x2.f32 %0, %1, %2;" : "=r"(r) : "f"(b), "f"(a)); return r; }
__device__ __forceinline__ unsigned hex2(unsigned x){ unsigned r; asm("ex2.approx.f16x2 %0, %1;" : "=r"(r) : "r"(x)); return r; }
__device__ __forceinline__ unsigned hadd2(unsigned a, unsigned b){ unsigned r; asm("add.rn.f16x2 %0, %1, %2;" : "=r"(r) : "r"(a), "r"(b)); return r; }

// ==== kernel 1: main pass (coefficient prep inlined, 268M exps) ====
// CTA = 128 i's  x  one 64-j chunk.
// smem: per (j, quad q) a 48B record: {A01,B01}{A23,B23}{G01,G23}
__global__ void __launch_bounds__(IB) btc_main(const float* __restrict__ z,
                                               const float* __restrict__ zm,
                                               const float* __restrict__ zl)
{
    __shared__ float sC[JC*NQ*12];   // 48KB exactly

    const int ch    = blockIdx.y;
    const int jbase = ch * JC;
    const int i     = blockIdx.x * IB + threadIdx.x;

    if (blockIdx.x == 0 && blockIdx.y == 0 && threadIdx.x == 0) d_ctr = 0;

    // ---- inline coefficient prep for this chunk's 64 j x 64 l ----
    #pragma unroll
    for (int k = 0; k < (JC*LATENT)/IB; k++) {
        int idx = threadIdx.x + k*IB;          // coalesced LDG
        int j = idx >> 6, l = idx & 63;
        float m  = zm[(jbase + j)*LATENT + l];
        float lv = zl[(jbase + j)*LATENT + l];
        float invs = ex2f(-lv * LOG2E_F);      // exp(-lv)
        float a = -0.5f * invs;
        int q = l >> 2;
        int aoff = (l & 2) * 2 + (l & 1);      // 0,1,4,5
        float* rec = &sC[(j*NQ + q)*12];
        rec[aoff    ] = a * LOG2E_F;                               // A
        rec[aoff + 2] = invs * m * LOG2E_F;                        // B
        rec[8 + (l&3)] = (a*m*m - 0.5f*(lv + LOG2PI_F)) * LOG2E_F; // G
    }
    __syncthreads();

    // ---- z row in registers, packed f32x2 ----
    u64 zr[NP];
    const float4* zp4 = (const float4*)(z + i*LATENT);
    #pragma unroll
    for (int q = 0; q < LATENT/4; q++) {
        float4 v = zp4[q];
        zr[2*q  ] = pkf2(v.x, v.y);
        zr[2*q+1] = pkf2(v.z, v.w);
    }

    unsigned hacc[NP];
    #pragma unroll
    for (int p = 0; p < NP; p++) hacc[p] = 0u;

    float M = -1e30f, T = 0.f;

    for (int jl = 0; jl < JC; jl++) {
        const ulonglong2* r2 = (const ulonglong2*)&sC[jl*NQ*12];
        u64 s2 = 0ull;
        #pragma unroll
        for (int q = 0; q < NQ; q++) {
            ulonglong2 ab0 = r2[3*q    ];        // {A01, B01}
            ulonglong2 ab1 = r2[3*q + 1];        // {A23, B23}
            ulonglong2 gg  = r2[3*q + 2];        // {G01, G23}
            u64 t0 = fma2(ab0.x, zr[2*q  ], ab0.y);
            u64 p0 = fma2(t0,    zr[2*q  ], gg.x);
            u64 t1 = fma2(ab1.x, zr[2*q+1], ab1.y);
            u64 p1 = fma2(t1,    zr[2*q+1], gg.y);
            s2 = add2(s2, p0);
            s2 = add2(s2, p1);
            float a0, a1, b0, b1;
            upk(p0, a0, a1);
            upk(p1, b0, b1);
            hacc[2*q  ] = hadd2(hacc[2*q  ], hex2(cvt_h2(a0, a1)));
            hacc[2*q+1] = hadd2(hacc[2*q+1], hex2(cvt_h2(b0, b1)));
        }
        float s0, s1; upk(s2, s0, s1);
        float S  = s0 + s1;                       // S_ij in log2 domain
        float nM = fmaxf(M, S);
        T = T * ex2f(M - nM) + ex2f(S - nM);      // branchless online LSE
        M = nM;
    }

    // write partials (coalesced over i)
    #pragma unroll
    for (int p = 0; p < NP; p++)
        d_accP[(ch*NP + p)*BATCH + i] = hacc[p];
    d_m2P[ch*BATCH + i] = M;
    d_t2P[ch*BATCH + i] = T;
}

// ==== kernel 2: stage-1 reduce. grid (8, 32): CTA = 256 i's x one pair ====
__global__ void __launch_bounds__(256) btc_stage1()
{
    const int p = blockIdx.y;
    const int i = blockIdx.x * 256 + threadIdx.x;
    float s0 = 0.f, s1 = 0.f;
    #pragma unroll
    for (int chn = 0; chn < NJ; chn++) {
        __half2 h = *reinterpret_cast<const __half2*>(&d_accP[(chn*NP + p)*BATCH + i]);
        float2 f = __half22float2(h);
        s0 += f.x; s1 += f.y;
    }
    d_lqp[p*BATCH + i] = lg2f(s0) + lg2f(s1);
}

// ==== kernel 3: finish — per-i combine + KL + last-block mean ====
__global__ void __launch_bounds__(256) btc_finish(const float* __restrict__ zm,
                                                  const float* __restrict__ zl,
                                                  float* __restrict__ out)
{
    __shared__ float sh[256];
    __shared__ unsigned s_done;

    const int i = blockIdx.x * 256 + threadIdx.x;

    float lqp = 0.f;
    #pragma unroll
    for (int p = 0; p < NP; p++) lqp += d_lqp[p*BATCH + i];

    float M = -1e30f, T = 0.f;
    #pragma unroll
    for (int chn = 0; chn < NJ; chn++) {
        float m = d_m2P[chn*BATCH + i];
        float t = d_t2P[chn*BATCH + i];
        float nM = fmaxf(M, m);
        T = T * ex2f(M - nM) + t * ex2f(m - nM);
        M = nM;
    }

    float kl = 0.f;
    const float4* m4 = (const float4*)(zm + i*LATENT);
    const float4* l4 = (const float4*)(zl + i*LATENT);
    #pragma unroll
    for (int q = 0; q < LATENT/4; q++) {
        float4 mm = m4[q], lv = l4[q];
        kl += mm.x*mm.x + ex2f(lv.x*LOG2E_F) - lv.x
            + mm.y*mm.y + ex2f(lv.y*LOG2E_F) - lv.y
            + mm.z*mm.z + ex2f(lv.z*LOG2E_F) - lv.z
            + mm.w*mm.w + ex2f(lv.w*LOG2E_F) - lv.w - 4.f;
    }

    float lq2 = M + lg2f(T);
    d_val[i] = 5.0f * LN2_F * (lq2 - lqp) + 0.5f * kl;

    // last CTA computes the deterministic mean
    __threadfence();
    if (threadIdx.x == 0) s_done = atomicAdd(&d_ctr, 1);
    __syncthreads();
    if (s_done == (BATCH/256) - 1) {
        __threadfence();
        float s = 0.f;
        for (int k = threadIdx.x; k < BATCH; k += 256) s += d_val[k];
        sh[threadIdx.x] = s;
        __syncthreads();
        for (int st = 128; st > 0; st >>= 1) {
            if (threadIdx.x < st) sh[threadIdx.x] += sh[threadIdx.x + st];
            __syncthreads();
        }
        if (threadIdx.x == 0) out[0] = sh[0] / (float)BATCH;
    }
}

extern "C" void kernel_launch(void* const* d_in, const int* in_sizes, int n_in,
                              void* d_out, int out_size)
{
    const float* z  = (const float*)d_in[0];
    const float* zm = (const float*)d_in[1];
    const float* zl = (const float*)d_in[2];
    (void)in_sizes; (void)n_in; (void)out_size;

    btc_main<<<dim3(BATCH/IB, NJ), IB>>>(z, zm, zl);
    btc_stage1<<<dim3(BATCH/256, NP), 256>>>();
    btc_finish<<<BATCH/256, 256>>>(zm, zl, (float*)d_out);
}

// round 6
// speedup vs baseline: 1.0042x; 1.0042x over previous
#include <cuda_runtime.h>
#include <cuda_fp16.h>

#define BATCH  2048
#define LATENT 64
#define NJ     64           // number of j-chunks
#define JC     (BATCH/NJ)   // 32 j per chunk
#define IB     128          // i per CTA
#define NP     (LATENT/2)   // 32 pairs
#define NQ     (LATENT/4)   // 16 quad-records

#define LOG2E_F   1.4426950408889634f
#define LN2_F     0.6931471805599453f
#define LOG2PI_F  1.8378770664093453f

// ---- device scratch (static; no allocation anywhere) ----
__device__ unsigned int d_accP[NJ*NP*BATCH]; // per-(chunk,pair,i) half2 partial sums (16MB)
__device__ float d_m2P[NJ*BATCH];            // per-(chunk,i) running max (log2 domain)
__device__ float d_t2P[NJ*BATCH];            // per-(chunk,i) running scaled sum
__device__ float d_lqp[NP*BATCH];            // per-(pair,i) lg2(s0)+lg2(s1)
__device__ float d_val[BATCH];               // per-i final value
__device__ unsigned int d_ctr;               // last-block counter

// ---- tiny PTX helpers ----
__device__ __forceinline__ float ex2f(float x){ float r; asm("ex2.approx.f32 %0, %1;" : "=f"(r) : "f"(x)); return r; }
__device__ __forceinline__ float lg2f(float x){ float r; asm("lg2.approx.f32 %0, %1;" : "=f"(r) : "f"(x)); return r; }
typedef unsigned long long u64;
__device__ __forceinline__ u64 fma2(u64 a, u64 b, u64 c){ u64 d; asm("fma.rn.f32x2 %0, %1, %2, %3;" : "=l"(d) : "l"(a), "l"(b), "l"(c)); return d; }
__device__ __forceinline__ u64 add2(u64 a, u64 b){ u64 d; asm("add.rn.f32x2 %0, %1, %2;" : "=l"(d) : "l"(a), "l"(b)); return d; }
__device__ __forceinline__ void upk(u64 v, float& lo, float& hi){ asm("mov.b64 {%0, %1}, %2;" : "=f"(lo), "=f"(hi) : "l"(v)); }
__device__ __forceinline__ u64 pkf2(float lo, float hi){ u64 r; asm("mov.b64 %0, {%1, %2};" : "=l"(r) : "f"(lo), "f"(hi)); return r; }
__device__ __forceinline__ unsigned cvt_h2(float a, float b){ unsigned r; asm("cvt.rn.f16x2.f32 %0, %1, %2;" : "=r"(r) : "f"(b), "f"(a)); return r; }
__device__ __forceinline__ unsigned hex2(unsigned x){ unsigned r; asm("ex2.approx.f16x2 %0, %1;" : "=r"(r) : "r"(x)); return r; }
__device__ __forceinline__ unsigned hadd2(unsigned a, unsigned b){ unsigned r; asm("add.rn.f16x2 %0, %1, %2;" : "=r"(r) : "r"(a), "r"(b)); return r; }

// ==== kernel 1: main pass (coefficient prep inlined, 268M exps) ====
// CTA = 128 i's  x  one 32-j chunk. (R4 geometry: 1024 CTAs, 24KB smem)
// smem: per (j, quad q) a 48B record: {A01,B01}{A23,B23}{G01,G23}
__global__ void __launch_bounds__(IB) btc_main(const float* __restrict__ z,
                                               const float* __restrict__ zm,
                                               const float* __restrict__ zl)
{
    __shared__ float sC[JC*NQ*12];   // 24KB

    const int ch    = blockIdx.y;
    const int jbase = ch * JC;
    const int i     = blockIdx.x * IB + threadIdx.x;

    if (blockIdx.x == 0 && blockIdx.y == 0 && threadIdx.x == 0) d_ctr = 0;

    // ---- inline coefficient prep for this chunk's 32 j x 64 l ----
    #pragma unroll
    for (int k = 0; k < (JC*LATENT)/IB; k++) {
        int idx = threadIdx.x + k*IB;          // coalesced LDG
        int j = idx >> 6, l = idx & 63;
        float m  = zm[(jbase + j)*LATENT + l];
        float lv = zl[(jbase + j)*LATENT + l];
        float invs = ex2f(-lv * LOG2E_F);      // exp(-lv)
        float a = -0.5f * invs;
        int q = l >> 2;
        int aoff = (l & 2) * 2 + (l & 1);      // 0,1,4,5
        float* rec = &sC[(j*NQ + q)*12];
        rec[aoff    ] = a * LOG2E_F;                               // A
        rec[aoff + 2] = invs * m * LOG2E_F;                        // B
        rec[8 + (l&3)] = (a*m*m - 0.5f*(lv + LOG2PI_F)) * LOG2E_F; // G
    }
    __syncthreads();

    // ---- z row in registers, packed f32x2 ----
    u64 zr[NP];
    const float4* zp4 = (const float4*)(z + i*LATENT);
    #pragma unroll
    for (int q = 0; q < LATENT/4; q++) {
        float4 v = zp4[q];
        zr[2*q  ] = pkf2(v.x, v.y);
        zr[2*q+1] = pkf2(v.z, v.w);
    }

    unsigned hacc[NP];
    #pragma unroll
    for (int p = 0; p < NP; p++) hacc[p] = 0u;

    float M = -1e30f, T = 0.f;

    for (int jl = 0; jl < JC; jl++) {
        const ulonglong2* r2 = (const ulonglong2*)&sC[jl*NQ*12];
        u64 s2 = 0ull;
        #pragma unroll
        for (int q = 0; q < NQ; q++) {
            ulonglong2 ab0 = r2[3*q    ];        // {A01, B01}
            ulonglong2 ab1 = r2[3*q + 1];        // {A23, B23}
            ulonglong2 gg  = r2[3*q + 2];        // {G01, G23}
            u64 t0 = fma2(ab0.x, zr[2*q  ], ab0.y);
            u64 p0 = fma2(t0,    zr[2*q  ], gg.x);
            u64 t1 = fma2(ab1.x, zr[2*q+1], ab1.y);
            u64 p1 = fma2(t1,    zr[2*q+1], gg.y);
            s2 = add2(s2, p0);
            s2 = add2(s2, p1);
            float a0, a1, b0, b1;
            upk(p0, a0, a1);
            upk(p1, b0, b1);
            hacc[2*q  ] = hadd2(hacc[2*q  ], hex2(cvt_h2(a0, a1)));
            hacc[2*q+1] = hadd2(hacc[2*q+1], hex2(cvt_h2(b0, b1)));
        }
        float s0, s1; upk(s2, s0, s1);
        float S  = s0 + s1;                       // S_ij in log2 domain
        float nM = fmaxf(M, S);
        T = T * ex2f(M - nM) + ex2f(S - nM);      // branchless online LSE
        M = nM;
    }

    // write partials (coalesced over i)
    #pragma unroll
    for (int p = 0; p < NP; p++)
        d_accP[(ch*NP + p)*BATCH + i] = hacc[p];
    d_m2P[ch*BATCH + i] = M;
    d_t2P[ch*BATCH + i] = T;
}

// ==== kernel 2: stage-1 reduce. grid (8, 32): CTA = 256 i's x one pair ====
__global__ void __launch_bounds__(256) btc_stage1()
{
    const int p = blockIdx.y;
    const int i = blockIdx.x * 256 + threadIdx.x;
    float s0 = 0.f, s1 = 0.f;
    #pragma unroll
    for (int chn = 0; chn < NJ; chn++) {
        __half2 h = *reinterpret_cast<const __half2*>(&d_accP[(chn*NP + p)*BATCH + i]);
        float2 f = __half22float2(h);
        s0 += f.x; s1 += f.y;
    }
    d_lqp[p*BATCH + i] = lg2f(s0) + lg2f(s1);
}

// ==== kernel 3: finish — per-i combine + KL + last-block mean ====
__global__ void __launch_bounds__(256) btc_finish(const float* __restrict__ zm,
                                                  const float* __restrict__ zl,
                                                  float* __restrict__ out)
{
    __shared__ float sh[256];
    __shared__ unsigned s_done;

    const int i = blockIdx.x * 256 + threadIdx.x;

    float lqp = 0.f;
    #pragma unroll
    for (int p = 0; p < NP; p++) lqp += d_lqp[p*BATCH + i];

    float M = -1e30f, T = 0.f;
    #pragma unroll
    for (int chn = 0; chn < NJ; chn++) {
        float m = d_m2P[chn*BATCH + i];
        float t = d_t2P[chn*BATCH + i];
        float nM = fmaxf(M, m);
        T = T * ex2f(M - nM) + t * ex2f(m - nM);
        M = nM;
    }

    float kl = 0.f;
    const float4* m4 = (const float4*)(zm + i*LATENT);
    const float4* l4 = (const float4*)(zl + i*LATENT);
    #pragma unroll
    for (int q = 0; q < LATENT/4; q++) {
        float4 mm = m4[q], lv = l4[q];
        kl += mm.x*mm.x + ex2f(lv.x*LOG2E_F) - lv.x
            + mm.y*mm.y + ex2f(lv.y*LOG2E_F) - lv.y
            + mm.z*mm.z + ex2f(lv.z*LOG2E_F) - lv.z
            + mm.w*mm.w + ex2f(lv.w*LOG2E_F) - lv.w - 4.f;
    }

    float lq2 = M + lg2f(T);
    d_val[i] = 5.0f * LN2_F * (lq2 - lqp) + 0.5f * kl;

    // last CTA computes the deterministic mean
    __threadfence();
    if (threadIdx.x == 0) s_done = atomicAdd(&d_ctr, 1);
    __syncthreads();
    if (s_done == (BATCH/256) - 1) {
        __threadfence();
        float s = 0.f;
        for (int k = threadIdx.x; k < BATCH; k += 256) s += d_val[k];
        sh[threadIdx.x] = s;
        __syncthreads();
        for (int st = 128; st > 0; st >>= 1) {
            if (threadIdx.x < st) sh[threadIdx.x] += sh[threadIdx.x + st];
            __syncthreads();
        }
        if (threadIdx.x == 0) out[0] = sh[0] / (float)BATCH;
    }
}

extern "C" void kernel_launch(void* const* d_in, const int* in_sizes, int n_in,
                              void* d_out, int out_size)
{
    const float* z  = (const float*)d_in[0];
    const float* zm = (const float*)d_in[1];
    const float* zl = (const float*)d_in[2];
    (void)in_sizes; (void)n_in; (void)out_size;

    btc_main<<<dim3(BATCH/IB, NJ), IB>>>(z, zm, zl);
    btc_stage1<<<dim3(BATCH/256, NP), 256>>>();
    btc_finish<<<BATCH/256, 256>>>(zm, zl, (float*)d_out);
}